// round 1
// baseline (speedup 1.0000x reference)
#include <cuda_runtime.h>
#include <math.h>

#define NE   8
#define HD   2048
#define ID   1024
#define TMAX 8192
#define TM   64
#define TN   64
#define KB   16
#define SPAD 68   // padded smem row (floats), multiple of 4 for float4, breaks bank conflicts

// -------- persistent device scratch (no allocation allowed) --------
__device__ int   g_cnt[NE];
__device__ int   g_off[NE + 1];
__device__ int   g_list[NE][TMAX];
__device__ float g_wt[NE][TMAX];
__device__ float g_h[TMAX * 2][ID];   // 64 MB: GLU activations for all routed (token,expert) pairs

// -------- kernel 0: zero y output + expert counters --------
__global__ void zero_kernel(float4* __restrict__ y, int n4) {
    int i = blockIdx.x * blockDim.x + threadIdx.x;
    if (i < n4) y[i] = make_float4(0.f, 0.f, 0.f, 0.f);
    if (blockIdx.x == 0 && threadIdx.x < NE) g_cnt[threadIdx.x] = 0;
}

// -------- kernel 1: router (one warp per token) --------
__global__ void router_kernel(const float* __restrict__ x,
                              const float* __restrict__ wg,
                              float* __restrict__ out_logits, int T) {
    int warp = (blockIdx.x * blockDim.x + threadIdx.x) >> 5;
    int lane = threadIdx.x & 31;
    if (warp >= T) return;
    const float* xr = x + (size_t)warp * HD;

    float acc[NE];
#pragma unroll
    for (int e = 0; e < NE; e++) acc[e] = 0.f;

    for (int h = lane; h < HD; h += 32) {
        float xv = xr[h];
#pragma unroll
        for (int e = 0; e < NE; e++) acc[e] = fmaf(xv, wg[e * HD + h], acc[e]);
    }
#pragma unroll
    for (int e = 0; e < NE; e++) {
#pragma unroll
        for (int o = 16; o > 0; o >>= 1)
            acc[e] += __shfl_xor_sync(0xffffffffu, acc[e], o);
    }

    if (out_logits && lane < NE)
        out_logits[(size_t)warp * NE + lane] = acc[lane];

    if (lane == 0) {
        // top-2 with first-index tie-breaking (matches jax.lax.top_k)
        int i0 = 0; float v0 = acc[0];
#pragma unroll
        for (int e = 1; e < NE; e++) if (acc[e] > v0) { v0 = acc[e]; i0 = e; }
        int i1 = -1; float v1 = -1e30f;
#pragma unroll
        for (int e = 0; e < NE; e++) if (e != i0 && acc[e] > v1) { v1 = acc[e]; i1 = e; }

        float e1 = expf(v1 - v0);
        float w0 = 1.f / (1.f + e1);
        float w1 = e1 * w0;

        int p0 = atomicAdd(&g_cnt[i0], 1);
        g_list[i0][p0] = warp; g_wt[i0][p0] = w0;
        int p1 = atomicAdd(&g_cnt[i1], 1);
        g_list[i1][p1] = warp; g_wt[i1][p1] = w1;
    }
}

// -------- kernel 2: exclusive prefix over expert counts --------
__global__ void offsets_kernel() {
    if (threadIdx.x == 0) {
        int s = 0;
        for (int e = 0; e < NE; e++) { g_off[e] = s; s += g_cnt[e]; }
        g_off[NE] = s;
    }
}

// -------- kernel 3: grouped FC + GLU:  h = silu(x@Wa^T) * (x@Wb^T) --------
__global__ __launch_bounds__(256) void fc_glu_kernel(const float* __restrict__ x,
                                                     const float* __restrict__ wfc) {
    int e   = blockIdx.z;
    int cnt = g_cnt[e];
    int m0  = blockIdx.y * TM;
    if (m0 >= cnt) return;
    int n0  = blockIdx.x * TN;
    const float* wfc_e = wfc + (size_t)e * 2 * ID * HD;

    __shared__ float As[KB][SPAD];
    __shared__ float Ba[KB][SPAD];
    __shared__ float Bb[KB][SPAD];
    __shared__ int   trow[TM];

    int tid = threadIdx.x;
    if (tid < TM) {
        int gi = m0 + tid;
        trow[tid] = (gi < cnt) ? g_list[e][gi] : g_list[e][cnt - 1];
    }
    __syncthreads();

    int tx = tid & 15, ty = tid >> 4;
    float accA[4][4], accB[4][4];
#pragma unroll
    for (int a = 0; a < 4; a++)
#pragma unroll
        for (int b = 0; b < 4; b++) { accA[a][b] = 0.f; accB[a][b] = 0.f; }

    for (int k0 = 0; k0 < HD; k0 += KB) {
#pragma unroll
        for (int r = 0; r < 4; r++) {
            int idx = tid + r * 256;
            int i = idx >> 4, k = idx & 15;
            As[k][i] = x[(size_t)trow[i] * HD + k0 + k];
            Ba[k][i] = wfc_e[(size_t)(n0 + i) * HD + k0 + k];
            Bb[k][i] = wfc_e[(size_t)(n0 + i + ID) * HD + k0 + k];
        }
        __syncthreads();
#pragma unroll
        for (int k = 0; k < KB; k++) {
            float4 av  = *(const float4*)&As[k][ty * 4];
            float4 bav = *(const float4*)&Ba[k][tx * 4];
            float4 bbv = *(const float4*)&Bb[k][tx * 4];
            float ar[4]  = {av.x,  av.y,  av.z,  av.w};
            float bar[4] = {bav.x, bav.y, bav.z, bav.w};
            float bbr[4] = {bbv.x, bbv.y, bbv.z, bbv.w};
#pragma unroll
            for (int a = 0; a < 4; a++)
#pragma unroll
                for (int b = 0; b < 4; b++) {
                    accA[a][b] = fmaf(ar[a], bar[b], accA[a][b]);
                    accB[a][b] = fmaf(ar[a], bbr[b], accB[a][b]);
                }
        }
        __syncthreads();
    }

    int off = g_off[e];
#pragma unroll
    for (int a = 0; a < 4; a++) {
        int gi = m0 + ty * 4 + a;
        if (gi < cnt) {
            float vs[4];
#pragma unroll
            for (int b = 0; b < 4; b++) {
                float av = accA[a][b];
                float s  = av / (1.f + expf(-av));   // silu
                vs[b] = s * accB[a][b];
            }
            float4 hv = make_float4(vs[0], vs[1], vs[2], vs[3]);
            *(float4*)&g_h[off + gi][n0 + tx * 4] = hv;
        }
    }
}

// -------- kernel 4: grouped proj + weighted scatter:  y[t] += w * (h @ Wp^T) --------
__global__ __launch_bounds__(256) void proj_kernel(const float* __restrict__ wproj,
                                                   float* __restrict__ out_y) {
    int e   = blockIdx.z;
    int cnt = g_cnt[e];
    int m0  = blockIdx.y * TM;
    if (m0 >= cnt) return;
    int n0  = blockIdx.x * TN;
    const float* wp_e = wproj + (size_t)e * HD * ID;

    __shared__ float As[KB][SPAD];
    __shared__ float Bs[KB][SPAD];
    __shared__ int   trow[TM];
    __shared__ float twt[TM];

    int tid = threadIdx.x;
    if (tid < TM) {
        int gi = m0 + tid;
        trow[tid] = (gi < cnt) ? g_list[e][gi] : 0;
        twt[tid]  = (gi < cnt) ? g_wt[e][gi] : 0.f;
    }
    __syncthreads();

    int off = g_off[e];
    int tx = tid & 15, ty = tid >> 4;
    float acc[4][4];
#pragma unroll
    for (int a = 0; a < 4; a++)
#pragma unroll
        for (int b = 0; b < 4; b++) acc[a][b] = 0.f;

    for (int k0 = 0; k0 < ID; k0 += KB) {
#pragma unroll
        for (int r = 0; r < 4; r++) {
            int idx = tid + r * 256;
            int i = idx >> 4, k = idx & 15;
            int gi = m0 + i; if (gi >= cnt) gi = cnt - 1;
            As[k][i] = g_h[off + gi][k0 + k];
            Bs[k][i] = wp_e[(size_t)(n0 + i) * ID + k0 + k];
        }
        __syncthreads();
#pragma unroll
        for (int k = 0; k < KB; k++) {
            float4 av = *(const float4*)&As[k][ty * 4];
            float4 bv = *(const float4*)&Bs[k][tx * 4];
            float ar[4] = {av.x, av.y, av.z, av.w};
            float br[4] = {bv.x, bv.y, bv.z, bv.w};
#pragma unroll
            for (int a = 0; a < 4; a++)
#pragma unroll
                for (int b = 0; b < 4; b++)
                    acc[a][b] = fmaf(ar[a], br[b], acc[a][b]);
        }
        __syncthreads();
    }

#pragma unroll
    for (int a = 0; a < 4; a++) {
        int li = ty * 4 + a;
        int gi = m0 + li;
        if (gi < cnt) {
            float w = twt[li];
            size_t base = (size_t)trow[li] * HD + n0 + tx * 4;
#pragma unroll
            for (int b = 0; b < 4; b++)
                atomicAdd(&out_y[base + b], w * acc[a][b]);
        }
    }
}

// -------- launch --------
extern "C" void kernel_launch(void* const* d_in, const int* in_sizes, int n_in,
                              void* d_out, int out_size) {
    const float* x     = (const float*)d_in[0];
    const float* wg    = (const float*)d_in[1];
    const float* wfc   = (const float*)d_in[2];
    const float* wproj = (const float*)d_in[3];
    float* out = (float*)d_out;

    int T = in_sizes[0] / HD;
    if (T > TMAX) T = TMAX;

    float* out_y = out;
    long long need = (long long)T * HD + (long long)T * NE;
    float* out_logits = ((long long)out_size >= need) ? out + (size_t)T * HD : nullptr;

    int n4 = (T * HD) / 4;
    zero_kernel<<<(n4 + 255) / 256, 256>>>((float4*)out_y, n4);
    router_kernel<<<(T * 32 + 255) / 256, 256>>>(x, wg, out_logits, T);
    offsets_kernel<<<1, 32>>>();

    dim3 g1(ID / TN, (T + TM - 1) / TM, NE);
    fc_glu_kernel<<<g1, 256>>>(x, wfc);

    dim3 g2(HD / TN, (T + TM - 1) / TM, NE);
    proj_kernel<<<g2, 256>>>(wproj, out_y);
}

// round 3
// speedup vs baseline: 2.7293x; 2.7293x over previous
#include <cuda_runtime.h>
#include <cuda_bf16.h>
#include <math.h>
#include <stdint.h>

#define NE   8
#define HD   2048
#define ID   1024
#define TMAX 8192
#define RMAX (2*TMAX)

#define KC    32                  // K elems per chunk
#define NST   3                   // pipeline stages
#define ROWB  80                  // smem bytes per tile row (64 data + 16 pad)
#define TILE_B (128*ROWB)         // 10240 B per matrix tile
#define STG_B  (4*TILE_B)         // Ahi,Alo,Bhi,Blo per stage
#define DSMEM  (NST*STG_B)        // 122880 B dynamic smem

// ---------------- persistent device scratch ----------------
__device__ int   g_cnt[NE];
__device__ int   g_off[NE + 1];
__device__ int   g_list[NE][TMAX];
__device__ float g_wt[NE][TMAX];
__device__ int4  g_slot[TMAX];                         // (e0,p0,e1,p1) per token
__device__ __align__(256) __nv_bfloat16 g_x_hi[(size_t)TMAX * HD];
__device__ __align__(256) __nv_bfloat16 g_x_lo[(size_t)TMAX * HD];
__device__ __align__(256) __nv_bfloat16 g_wfc_hi[(size_t)NE * 2 * ID * HD];
__device__ __align__(256) __nv_bfloat16 g_wfc_lo[(size_t)NE * 2 * ID * HD];
__device__ __align__(256) __nv_bfloat16 g_wp_hi[(size_t)NE * HD * ID];
__device__ __align__(256) __nv_bfloat16 g_wp_lo[(size_t)NE * HD * ID];
__device__ __align__(256) __nv_bfloat16 g_h_hi[(size_t)RMAX * ID];
__device__ __align__(256) __nv_bfloat16 g_h_lo[(size_t)RMAX * ID];
__device__ __align__(256) float g_fc[(size_t)RMAX * 2048];   // FC output, then proj output

// ---------------- PTX helpers (generic, non-'a') ----------------
__device__ __forceinline__ uint32_t smem_u32(const void* p) {
    uint32_t a;
    asm("{ .reg .u64 t; cvta.to.shared.u64 t, %1; cvt.u32.u64 %0, t; }" : "=r"(a) : "l"(p));
    return a;
}
__device__ __forceinline__ void cp16(uint32_t d, const void* s) {
    asm volatile("cp.async.cg.shared.global [%0], [%1], 16;\n" :: "r"(d), "l"(s));
}
#define CP_COMMIT() asm volatile("cp.async.commit_group;\n" ::: "memory")
#define CP_WAIT1()  asm volatile("cp.async.wait_group 1;\n" ::: "memory")

__device__ __forceinline__ void ldsm4(uint32_t r[4], uint32_t addr) {
    asm volatile("ldmatrix.sync.aligned.m8n8.x4.shared.b16 {%0,%1,%2,%3}, [%4];\n"
                 : "=r"(r[0]), "=r"(r[1]), "=r"(r[2]), "=r"(r[3]) : "r"(addr));
}
__device__ __forceinline__ void ldsm2(uint32_t r[2], uint32_t addr) {
    asm volatile("ldmatrix.sync.aligned.m8n8.x2.shared.b16 {%0,%1}, [%2];\n"
                 : "=r"(r[0]), "=r"(r[1]) : "r"(addr));
}
__device__ __forceinline__ void mma_bf16(float c[4], const uint32_t a[4], const uint32_t b[2]) {
    asm volatile(
        "mma.sync.aligned.m16n8k16.row.col.f32.bf16.bf16.f32 "
        "{%0,%1,%2,%3}, {%4,%5,%6,%7}, {%8,%9}, {%0,%1,%2,%3};\n"
        : "+f"(c[0]), "+f"(c[1]), "+f"(c[2]), "+f"(c[3])
        : "r"(a[0]), "r"(a[1]), "r"(a[2]), "r"(a[3]), "r"(b[0]), "r"(b[1]));
}

// ---------------- kernel 0: zero counters ----------------
__global__ void zero_cnt_kernel() {
    if (threadIdx.x < NE) g_cnt[threadIdx.x] = 0;
}

// ---------------- kernel 1: router (one warp per token) ----------------
__global__ void router_kernel(const float* __restrict__ x,
                              const float* __restrict__ wg,
                              float* __restrict__ out_logits, int T) {
    int warp = (blockIdx.x * blockDim.x + threadIdx.x) >> 5;
    int lane = threadIdx.x & 31;
    if (warp >= T) return;
    const float* xr = x + (size_t)warp * HD;

    float acc[NE];
#pragma unroll
    for (int e = 0; e < NE; e++) acc[e] = 0.f;
    for (int h = lane; h < HD; h += 32) {
        float xv = xr[h];
#pragma unroll
        for (int e = 0; e < NE; e++) acc[e] = fmaf(xv, wg[e * HD + h], acc[e]);
    }
#pragma unroll
    for (int e = 0; e < NE; e++) {
#pragma unroll
        for (int o = 16; o > 0; o >>= 1)
            acc[e] += __shfl_xor_sync(0xffffffffu, acc[e], o);
    }
    if (out_logits && lane < NE)
        out_logits[(size_t)warp * NE + lane] = acc[lane];
    if (lane == 0) {
        int i0 = 0; float v0 = acc[0];
#pragma unroll
        for (int e = 1; e < NE; e++) if (acc[e] > v0) { v0 = acc[e]; i0 = e; }
        int i1 = -1; float v1 = -1e30f;
#pragma unroll
        for (int e = 0; e < NE; e++) if (e != i0 && acc[e] > v1) { v1 = acc[e]; i1 = e; }
        float e1 = expf(v1 - v0);
        float w0 = 1.f / (1.f + e1);
        float w1 = e1 * w0;
        int p0 = atomicAdd(&g_cnt[i0], 1);
        g_list[i0][p0] = warp; g_wt[i0][p0] = w0;
        int p1 = atomicAdd(&g_cnt[i1], 1);
        g_list[i1][p1] = warp; g_wt[i1][p1] = w1;
        g_slot[warp] = make_int4(i0, p0, i1, p1);
    }
}

// ---------------- kernel 2: prefix offsets ----------------
__global__ void offsets_kernel() {
    if (threadIdx.x == 0) {
        int s = 0;
        for (int e = 0; e < NE; e++) { g_off[e] = s; s += g_cnt[e]; }
        g_off[NE] = s;
    }
}

// ---------------- split: fp32 -> bf16 hi + bf16 lo ----------------
__device__ __forceinline__ void split4_store(float4 v, __nv_bfloat16* hi, __nv_bfloat16* lo, size_t i) {
    float f[4] = {v.x, v.y, v.z, v.w};
    __nv_bfloat16 h[4], l[4];
#pragma unroll
    for (int j = 0; j < 4; j++) {
        h[j] = __float2bfloat16(f[j]);
        l[j] = __float2bfloat16(f[j] - __bfloat162float(h[j]));
    }
    __nv_bfloat162 p0, p1;
    p0.x = h[0]; p0.y = h[1]; p1.x = h[2]; p1.y = h[3];
    *(__nv_bfloat162*)(hi + i) = p0; *(__nv_bfloat162*)(hi + i + 2) = p1;
    p0.x = l[0]; p0.y = l[1]; p1.x = l[2]; p1.y = l[3];
    *(__nv_bfloat162*)(lo + i) = p0; *(__nv_bfloat162*)(lo + i + 2) = p1;
}
__global__ void split_x_kernel(const float* __restrict__ src, int n4) {
    int i = blockIdx.x * blockDim.x + threadIdx.x;
    if (i < n4) split4_store(*(const float4*)(src + (size_t)i * 4), g_x_hi, g_x_lo, (size_t)i * 4);
}
__global__ void split_wfc_kernel(const float* __restrict__ src, int n4) {
    int i = blockIdx.x * blockDim.x + threadIdx.x;
    if (i < n4) split4_store(*(const float4*)(src + (size_t)i * 4), g_wfc_hi, g_wfc_lo, (size_t)i * 4);
}
__global__ void split_wp_kernel(const float* __restrict__ src, int n4) {
    int i = blockIdx.x * blockDim.x + threadIdx.x;
    if (i < n4) split4_store(*(const float4*)(src + (size_t)i * 4), g_wp_hi, g_wp_lo, (size_t)i * 4);
}

// ---------------- kernel 3: FC GEMM (gathered A) -> g_fc fp32 ----------------
__global__ void __launch_bounds__(256, 1) fc_mma_kernel() {
    extern __shared__ char sm[];
    __shared__ int trow[128];
    int e = blockIdx.z, cnt = g_cnt[e];
    int m0 = blockIdx.y * 128;
    if (m0 >= cnt) return;
    int n0 = blockIdx.x * 128;
    int tid = threadIdx.x;
    if (tid < 128) { int gi = m0 + tid; trow[tid] = g_list[e][gi < cnt ? gi : cnt - 1]; }
    __syncthreads();
    uint32_t sb = smem_u32(sm);

    // loader assignment: 2 threads per row; 32B (2x16B) each
    int lrow = tid >> 1;
    int lc   = (tid & 1) * 32;          // byte offset within 64B of row data
    int tok  = trow[lrow];
    const char* gAh = (const char*)(g_x_hi + (size_t)tok * HD) + lc;
    const char* gAl = (const char*)(g_x_lo + (size_t)tok * HD) + lc;
    size_t brow = ((size_t)e * 2 * ID + n0 + lrow) * HD;
    const char* gBh = (const char*)(g_wfc_hi + brow) + lc;
    const char* gBl = (const char*)(g_wfc_lo + brow) + lc;
    uint32_t sd = sb + lrow * ROWB + lc;

    auto load_stage = [&](int s, int kc) {
        uint32_t d = sd + s * STG_B;
        int go = kc * (KC * 2);         // bytes
        cp16(d,                gAh + go); cp16(d + 16,              gAh + go + 16);
        cp16(d + TILE_B,       gAl + go); cp16(d + TILE_B + 16,     gAl + go + 16);
        cp16(d + 2 * TILE_B,   gBh + go); cp16(d + 2 * TILE_B + 16, gBh + go + 16);
        cp16(d + 3 * TILE_B,   gBl + go); cp16(d + 3 * TILE_B + 16, gBl + go + 16);
    };

    int wid = tid >> 5, lane = tid & 31;
    int wm = (wid & 1) * 64, wn = (wid >> 1) * 32;
    uint32_t a_base = sb + (wm + (lane & 15)) * ROWB + ((lane & 16) ? 16 : 0);
    uint32_t b_base = sb + 2 * TILE_B + (wn + (lane & 7)) * ROWB + ((lane & 8) ? 16 : 0);

    float acc[4][4][4];
#pragma unroll
    for (int mt = 0; mt < 4; mt++)
#pragma unroll
        for (int nt = 0; nt < 4; nt++)
#pragma unroll
            for (int k = 0; k < 4; k++) acc[mt][nt][k] = 0.f;

    const int NK = HD / KC;             // 64
    for (int s = 0; s < NST - 1; s++) { load_stage(s, s); CP_COMMIT(); }

    for (int kc = 0; kc < NK; kc++) {
        CP_WAIT1();
        __syncthreads();
        if (kc + NST - 1 < NK) load_stage((kc + NST - 1) % NST, kc + NST - 1);
        CP_COMMIT();
        uint32_t st = (uint32_t)(kc % NST) * STG_B;
#pragma unroll
        for (int ks = 0; ks < 2; ks++) {
            uint32_t ah[4][4], al[4][4], bh[4][2], bl[4][2];
#pragma unroll
            for (int mt = 0; mt < 4; mt++) {
                ldsm4(ah[mt], a_base + st + mt * 16 * ROWB + ks * 32);
                ldsm4(al[mt], a_base + st + TILE_B + mt * 16 * ROWB + ks * 32);
            }
#pragma unroll
            for (int nt = 0; nt < 4; nt++) {
                ldsm2(bh[nt], b_base + st + nt * 8 * ROWB + ks * 32);
                ldsm2(bl[nt], b_base + st + TILE_B + nt * 8 * ROWB + ks * 32);
            }
#pragma unroll
            for (int mt = 0; mt < 4; mt++)
#pragma unroll
                for (int nt = 0; nt < 4; nt++) {
                    mma_bf16(acc[mt][nt], ah[mt], bh[nt]);
                    mma_bf16(acc[mt][nt], ah[mt], bl[nt]);
                    mma_bf16(acc[mt][nt], al[mt], bh[nt]);
                }
        }
    }

    int g = lane >> 2, t = lane & 3;
    int roff = g_off[e];
#pragma unroll
    for (int mt = 0; mt < 4; mt++) {
#pragma unroll
        for (int half = 0; half < 2; half++) {
            int r = wm + mt * 16 + g + half * 8;
            int gi = m0 + r;
            if (gi < cnt) {
                float* orow = g_fc + (size_t)(roff + gi) * 2048 + n0 + wn;
#pragma unroll
                for (int nt = 0; nt < 4; nt++) {
                    float2 v = half ? make_float2(acc[mt][nt][2], acc[mt][nt][3])
                                    : make_float2(acc[mt][nt][0], acc[mt][nt][1]);
                    *(float2*)(orow + nt * 8 + t * 2) = v;
                }
            }
        }
    }
}

// ---------------- kernel 4: GLU + split -> g_h hi/lo ----------------
__global__ void glu_kernel() {
    int R = g_off[NE];
    int idx = blockIdx.x * blockDim.x + threadIdx.x;
    int r = idx >> 8;                   // ID/4 = 256 quads per row
    if (r >= R) return;
    int c = (idx & 255) * 4;
    const float* row = g_fc + (size_t)r * 2048;
    float4 a = *(const float4*)(row + c);
    float4 b = *(const float4*)(row + 1024 + c);
    float fa[4] = {a.x, a.y, a.z, a.w};
    float fb[4] = {b.x, b.y, b.z, b.w};
    size_t o = (size_t)r * ID + c;
    __nv_bfloat16 h[4], l[4];
#pragma unroll
    for (int j = 0; j < 4; j++) {
        float gv = fa[j] / (1.f + expf(-fa[j])) * fb[j];
        h[j] = __float2bfloat16(gv);
        l[j] = __float2bfloat16(gv - __bfloat162float(h[j]));
    }
    __nv_bfloat162 p0, p1;
    p0.x = h[0]; p0.y = h[1]; p1.x = h[2]; p1.y = h[3];
    *(__nv_bfloat162*)(g_h_hi + o) = p0; *(__nv_bfloat162*)(g_h_hi + o + 2) = p1;
    p0.x = l[0]; p0.y = l[1]; p1.x = l[2]; p1.y = l[3];
    *(__nv_bfloat162*)(g_h_lo + o) = p0; *(__nv_bfloat162*)(g_h_lo + o + 2) = p1;
}

// ---------------- kernel 5: proj GEMM -> g_fc fp32 (reused) ----------------
__global__ void __launch_bounds__(256, 1) proj_mma_kernel() {
    extern __shared__ char sm[];
    int e = blockIdx.z, cnt = g_cnt[e];
    int m0 = blockIdx.y * 128;
    if (m0 >= cnt) return;
    int n0 = blockIdx.x * 128;
    int tid = threadIdx.x;
    uint32_t sb = smem_u32(sm);
    int roff = g_off[e];

    int lrow = tid >> 1;
    int lc   = (tid & 1) * 32;
    int gi0  = m0 + lrow;
    int gic  = gi0 < cnt ? gi0 : cnt - 1;
    size_t arow = (size_t)(roff + gic) * ID;
    const char* gAh = (const char*)(g_h_hi + arow) + lc;
    const char* gAl = (const char*)(g_h_lo + arow) + lc;
    size_t brow = ((size_t)e * HD + n0 + lrow) * ID;
    const char* gBh = (const char*)(g_wp_hi + brow) + lc;
    const char* gBl = (const char*)(g_wp_lo + brow) + lc;
    uint32_t sd = sb + lrow * ROWB + lc;

    auto load_stage = [&](int s, int kc) {
        uint32_t d = sd + s * STG_B;
        int go = kc * (KC * 2);
        cp16(d,                gAh + go); cp16(d + 16,              gAh + go + 16);
        cp16(d + TILE_B,       gAl + go); cp16(d + TILE_B + 16,     gAl + go + 16);
        cp16(d + 2 * TILE_B,   gBh + go); cp16(d + 2 * TILE_B + 16, gBh + go + 16);
        cp16(d + 3 * TILE_B,   gBl + go); cp16(d + 3 * TILE_B + 16, gBl + go + 16);
    };

    int wid = tid >> 5, lane = tid & 31;
    int wm = (wid & 1) * 64, wn = (wid >> 1) * 32;
    uint32_t a_base = sb + (wm + (lane & 15)) * ROWB + ((lane & 16) ? 16 : 0);
    uint32_t b_base = sb + 2 * TILE_B + (wn + (lane & 7)) * ROWB + ((lane & 8) ? 16 : 0);

    float acc[4][4][4];
#pragma unroll
    for (int mt = 0; mt < 4; mt++)
#pragma unroll
        for (int nt = 0; nt < 4; nt++)
#pragma unroll
            for (int k = 0; k < 4; k++) acc[mt][nt][k] = 0.f;

    const int NK = ID / KC;             // 32
    for (int s = 0; s < NST - 1; s++) { load_stage(s, s); CP_COMMIT(); }

    for (int kc = 0; kc < NK; kc++) {
        CP_WAIT1();
        __syncthreads();
        if (kc + NST - 1 < NK) load_stage((kc + NST - 1) % NST, kc + NST - 1);
        CP_COMMIT();
        uint32_t st = (uint32_t)(kc % NST) * STG_B;
#pragma unroll
        for (int ks = 0; ks < 2; ks++) {
            uint32_t ah[4][4], al[4][4], bh[4][2], bl[4][2];
#pragma unroll
            for (int mt = 0; mt < 4; mt++) {
                ldsm4(ah[mt], a_base + st + mt * 16 * ROWB + ks * 32);
                ldsm4(al[mt], a_base + st + TILE_B + mt * 16 * ROWB + ks * 32);
            }
#pragma unroll
            for (int nt = 0; nt < 4; nt++) {
                ldsm2(bh[nt], b_base + st + nt * 8 * ROWB + ks * 32);
                ldsm2(bl[nt], b_base + st + TILE_B + nt * 8 * ROWB + ks * 32);
            }
#pragma unroll
            for (int mt = 0; mt < 4; mt++)
#pragma unroll
                for (int nt = 0; nt < 4; nt++) {
                    mma_bf16(acc[mt][nt], ah[mt], bh[nt]);
                    mma_bf16(acc[mt][nt], ah[mt], bl[nt]);
                    mma_bf16(acc[mt][nt], al[mt], bh[nt]);
                }
        }
    }

    int g = lane >> 2, t = lane & 3;
#pragma unroll
    for (int mt = 0; mt < 4; mt++) {
#pragma unroll
        for (int half = 0; half < 2; half++) {
            int r = wm + mt * 16 + g + half * 8;
            int gi = m0 + r;
            if (gi < cnt) {
                float* orow = g_fc + (size_t)(roff + gi) * 2048 + n0 + wn;
#pragma unroll
                for (int nt = 0; nt < 4; nt++) {
                    float2 v = half ? make_float2(acc[mt][nt][2], acc[mt][nt][3])
                                    : make_float2(acc[mt][nt][0], acc[mt][nt][1]);
                    *(float2*)(orow + nt * 8 + t * 2) = v;
                }
            }
        }
    }
}

// ---------------- kernel 6: combine:  y[t] = w0*p[row0] + w1*p[row1] ----------------
__global__ void combine_kernel(float* __restrict__ out_y, int T) {
    int idx = blockIdx.x * blockDim.x + threadIdx.x;
    int t = idx >> 9;                   // HD/4 = 512 quads per token
    if (t >= T) return;
    int c = (idx & 511) * 4;
    int4 s = g_slot[t];
    int r0 = g_off[s.x] + s.y;
    int r1 = g_off[s.z] + s.w;
    float w0 = g_wt[s.x][s.y];
    float w1 = g_wt[s.z][s.w];
    float4 p0 = *(const float4*)(g_fc + (size_t)r0 * 2048 + c);
    float4 p1 = *(const float4*)(g_fc + (size_t)r1 * 2048 + c);
    float4 v;
    v.x = w0 * p0.x + w1 * p1.x;
    v.y = w0 * p0.y + w1 * p1.y;
    v.z = w0 * p0.z + w1 * p1.z;
    v.w = w0 * p0.w + w1 * p1.w;
    *(float4*)(out_y + (size_t)t * HD + c) = v;
}

// ---------------- launch ----------------
extern "C" void kernel_launch(void* const* d_in, const int* in_sizes, int n_in,
                              void* d_out, int out_size) {
    const float* x   = (const float*)d_in[0];
    const float* wg  = (const float*)d_in[1];
    const float* wfc = (const float*)d_in[2];
    const float* wp  = (const float*)d_in[3];
    float* out = (float*)d_out;

    int T = in_sizes[0] / HD;
    if (T > TMAX) T = TMAX;

    float* out_y = out;
    long long need = (long long)T * HD + (long long)T * NE;
    float* out_logits = ((long long)out_size >= need) ? out + (size_t)T * HD : nullptr;

    cudaFuncSetAttribute(fc_mma_kernel,   cudaFuncAttributeMaxDynamicSharedMemorySize, DSMEM);
    cudaFuncSetAttribute(proj_mma_kernel, cudaFuncAttributeMaxDynamicSharedMemorySize, DSMEM);

    zero_cnt_kernel<<<1, 32>>>();
    router_kernel<<<(T * 32 + 255) / 256, 256>>>(x, wg, out_logits, T);
    offsets_kernel<<<1, 32>>>();

    int n4 = (T * HD) / 4;
    split_x_kernel<<<(n4 + 255) / 256, 256>>>(x, n4);
    int n4fc = NE * 2 * ID * HD / 4;
    split_wfc_kernel<<<(n4fc + 255) / 256, 256>>>(wfc, n4fc);
    int n4wp = NE * HD * ID / 4;
    split_wp_kernel<<<(n4wp + 255) / 256, 256>>>(wp, n4wp);

    dim3 g1(2 * ID / 128, TMAX / 128, NE);   // (16, 64, 8)
    fc_mma_kernel<<<g1, 256, DSMEM>>>();

    int nglu = RMAX * (ID / 4);
    glu_kernel<<<nglu / 256, 256>>>();

    dim3 g2(HD / 128, TMAX / 128, NE);       // (16, 64, 8)
    proj_mma_kernel<<<g2, 256, DSMEM>>>();

    int ncmb = T * (HD / 4);
    combine_kernel<<<(ncmb + 255) / 256, 256>>>(out_y, T);
}

// round 4
// speedup vs baseline: 2.7781x; 1.0179x over previous
#include <cuda_runtime.h>
#include <cuda_bf16.h>
#include <math.h>
#include <stdint.h>

#define NE   8
#define HD   2048
#define ID   1024
#define TMAX 8192
#define RMAX (2*TMAX)

#define KC     32                   // K elems per chunk
#define NST    3                    // pipeline stages
#define ROWB   80                   // smem bytes per tile row (64 data + 16 pad)
#define A_ROWS 256
#define B_ROWS 128
#define A_T    (A_ROWS*ROWB)        // 20480
#define B_T    (B_ROWS*ROWB)        // 10240
#define STG_B  (2*A_T + 2*B_T)      // 61440 per stage (Ahi,Alo,Bhi,Blo)
#define DSMEM  (NST*STG_B)          // 184320

// ---------------- persistent device scratch ----------------
__device__ int   g_cnt[NE];
__device__ int   g_off[NE + 1];
__device__ int   g_list[NE][TMAX];
__device__ float g_wt[NE][TMAX];
__device__ int4  g_slot[TMAX];
__device__ __align__(256) __nv_bfloat16 g_x_hi[(size_t)TMAX * HD];
__device__ __align__(256) __nv_bfloat16 g_x_lo[(size_t)TMAX * HD];
__device__ __align__(256) __nv_bfloat16 g_wfc_hi[(size_t)NE * 2 * ID * HD];
__device__ __align__(256) __nv_bfloat16 g_wfc_lo[(size_t)NE * 2 * ID * HD];
__device__ __align__(256) __nv_bfloat16 g_wp_hi[(size_t)NE * HD * ID];
__device__ __align__(256) __nv_bfloat16 g_wp_lo[(size_t)NE * HD * ID];
__device__ __align__(256) __nv_bfloat16 g_h_hi[(size_t)RMAX * ID];
__device__ __align__(256) __nv_bfloat16 g_h_lo[(size_t)RMAX * ID];
__device__ __align__(256) float g_fc[(size_t)RMAX * 2048];

// ---------------- PTX helpers ----------------
__device__ __forceinline__ uint32_t smem_u32(const void* p) {
    uint32_t a;
    asm("{ .reg .u64 t; cvta.to.shared.u64 t, %1; cvt.u32.u64 %0, t; }" : "=r"(a) : "l"(p));
    return a;
}
__device__ __forceinline__ void cp16(uint32_t d, const void* s) {
    asm volatile("cp.async.cg.shared.global [%0], [%1], 16;\n" :: "r"(d), "l"(s));
}
#define CP_COMMIT() asm volatile("cp.async.commit_group;\n" ::: "memory")
#define CP_WAIT1()  asm volatile("cp.async.wait_group 1;\n" ::: "memory")

__device__ __forceinline__ void ldsm4(uint32_t r[4], uint32_t addr) {
    asm volatile("ldmatrix.sync.aligned.m8n8.x4.shared.b16 {%0,%1,%2,%3}, [%4];\n"
                 : "=r"(r[0]), "=r"(r[1]), "=r"(r[2]), "=r"(r[3]) : "r"(addr));
}
__device__ __forceinline__ void ldsm2(uint32_t r[2], uint32_t addr) {
    asm volatile("ldmatrix.sync.aligned.m8n8.x2.shared.b16 {%0,%1}, [%2];\n"
                 : "=r"(r[0]), "=r"(r[1]) : "r"(addr));
}
__device__ __forceinline__ void mma_bf16(float c[4], const uint32_t a[4], const uint32_t b[2]) {
    asm volatile(
        "mma.sync.aligned.m16n8k16.row.col.f32.bf16.bf16.f32 "
        "{%0,%1,%2,%3}, {%4,%5,%6,%7}, {%8,%9}, {%0,%1,%2,%3};\n"
        : "+f"(c[0]), "+f"(c[1]), "+f"(c[2]), "+f"(c[3])
        : "r"(a[0]), "r"(a[1]), "r"(a[2]), "r"(a[3]), "r"(b[0]), "r"(b[1]));
}

// ---------------- kernel 0: zero counters ----------------
__global__ void zero_cnt_kernel() {
    if (threadIdx.x < NE) g_cnt[threadIdx.x] = 0;
}

// ---------------- kernel 1: router ----------------
__global__ void router_kernel(const float* __restrict__ x,
                              const float* __restrict__ wg,
                              float* __restrict__ out_logits, int T) {
    int warp = (blockIdx.x * blockDim.x + threadIdx.x) >> 5;
    int lane = threadIdx.x & 31;
    if (warp >= T) return;
    const float* xr = x + (size_t)warp * HD;

    float acc[NE];
#pragma unroll
    for (int e = 0; e < NE; e++) acc[e] = 0.f;
    for (int h = lane; h < HD; h += 32) {
        float xv = xr[h];
#pragma unroll
        for (int e = 0; e < NE; e++) acc[e] = fmaf(xv, wg[e * HD + h], acc[e]);
    }
#pragma unroll
    for (int e = 0; e < NE; e++) {
#pragma unroll
        for (int o = 16; o > 0; o >>= 1)
            acc[e] += __shfl_xor_sync(0xffffffffu, acc[e], o);
    }
    if (out_logits && lane < NE)
        out_logits[(size_t)warp * NE + lane] = acc[lane];
    if (lane == 0) {
        int i0 = 0; float v0 = acc[0];
#pragma unroll
        for (int e = 1; e < NE; e++) if (acc[e] > v0) { v0 = acc[e]; i0 = e; }
        int i1 = -1; float v1 = -1e30f;
#pragma unroll
        for (int e = 0; e < NE; e++) if (e != i0 && acc[e] > v1) { v1 = acc[e]; i1 = e; }
        float e1 = expf(v1 - v0);
        float w0 = 1.f / (1.f + e1);
        float w1 = e1 * w0;
        int p0 = atomicAdd(&g_cnt[i0], 1);
        g_list[i0][p0] = warp; g_wt[i0][p0] = w0;
        int p1 = atomicAdd(&g_cnt[i1], 1);
        g_list[i1][p1] = warp; g_wt[i1][p1] = w1;
        g_slot[warp] = make_int4(i0, p0, i1, p1);
    }
}

// ---------------- kernel 2: prefix offsets ----------------
__global__ void offsets_kernel() {
    if (threadIdx.x == 0) {
        int s = 0;
        for (int e = 0; e < NE; e++) { g_off[e] = s; s += g_cnt[e]; }
        g_off[NE] = s;
    }
}

// ---------------- split: fp32 -> bf16 hi + bf16 lo ----------------
__device__ __forceinline__ void split4_store(float4 v, __nv_bfloat16* hi, __nv_bfloat16* lo, size_t i) {
    float f[4] = {v.x, v.y, v.z, v.w};
    __nv_bfloat16 h[4], l[4];
#pragma unroll
    for (int j = 0; j < 4; j++) {
        h[j] = __float2bfloat16(f[j]);
        l[j] = __float2bfloat16(f[j] - __bfloat162float(h[j]));
    }
    __nv_bfloat162 p0, p1;
    p0.x = h[0]; p0.y = h[1]; p1.x = h[2]; p1.y = h[3];
    *(__nv_bfloat162*)(hi + i) = p0; *(__nv_bfloat162*)(hi + i + 2) = p1;
    p0.x = l[0]; p0.y = l[1]; p1.x = l[2]; p1.y = l[3];
    *(__nv_bfloat162*)(lo + i) = p0; *(__nv_bfloat162*)(lo + i + 2) = p1;
}
__global__ void split_x_kernel(const float* __restrict__ src, int n4) {
    int i = blockIdx.x * blockDim.x + threadIdx.x;
    if (i < n4) split4_store(*(const float4*)(src + (size_t)i * 4), g_x_hi, g_x_lo, (size_t)i * 4);
}
__global__ void split_wfc_kernel(const float* __restrict__ src, int n4) {
    int i = blockIdx.x * blockDim.x + threadIdx.x;
    if (i < n4) split4_store(*(const float4*)(src + (size_t)i * 4), g_wfc_hi, g_wfc_lo, (size_t)i * 4);
}
__global__ void split_wp_kernel(const float* __restrict__ src, int n4) {
    int i = blockIdx.x * blockDim.x + threadIdx.x;
    if (i < n4) split4_store(*(const float4*)(src + (size_t)i * 4), g_wp_hi, g_wp_lo, (size_t)i * 4);
}

// ================= GEMM mainloop (shared by FC and proj) =================
// CTA tile 256x128, 512 threads, 16 warps of 64x32, 3-term bf16 split.
struct GemmPtrs {
    const char *gAh, *gAl, *gBh, *gBl;   // per-thread source base (row+offset applied)
};

__device__ __forceinline__ void gemm_mainloop(
    uint32_t sb, const GemmPtrs& p, uint32_t sd_a, uint32_t sd_b,
    int NK, float acc[4][4][4],
    uint32_t a_base, uint32_t b_base)
{
    auto load_stage = [&](int s, int kc) {
        uint32_t st = (uint32_t)s * STG_B;
        int go = kc * (KC * 2);
        uint32_t da = sd_a + st;
        cp16(da,           p.gAh + go); cp16(da + 16,           p.gAh + go + 16);
        cp16(da + A_T,     p.gAl + go); cp16(da + A_T + 16,     p.gAl + go + 16);
        uint32_t db = sd_b + st;
        cp16(db,           p.gBh + go);
        cp16(db + B_T,     p.gBl + go);
    };

    for (int s = 0; s < NST - 1; s++) { load_stage(s, s); CP_COMMIT(); }

    for (int kc = 0; kc < NK; kc++) {
        CP_WAIT1();
        __syncthreads();
        if (kc + NST - 1 < NK) load_stage((kc + NST - 1) % NST, kc + NST - 1);
        CP_COMMIT();
        uint32_t st = (uint32_t)(kc % NST) * STG_B;
#pragma unroll
        for (int ks = 0; ks < 2; ks++) {
            uint32_t bh[4][2], bl[4][2];
#pragma unroll
            for (int nt = 0; nt < 4; nt++) {
                ldsm2(bh[nt], b_base + st + nt * 8 * ROWB + ks * 32);
                ldsm2(bl[nt], b_base + st + B_T + nt * 8 * ROWB + ks * 32);
            }
#pragma unroll
            for (int mt = 0; mt < 4; mt++) {
                uint32_t ah[4], al[4];
                ldsm4(ah, a_base + st + mt * 16 * ROWB + ks * 32);
                ldsm4(al, a_base + st + A_T + mt * 16 * ROWB + ks * 32);
#pragma unroll
                for (int nt = 0; nt < 4; nt++) {
                    mma_bf16(acc[mt][nt], ah, bh[nt]);
                    mma_bf16(acc[mt][nt], ah, bl[nt]);
                    mma_bf16(acc[mt][nt], al, bh[nt]);
                }
            }
        }
    }
}

// ---------------- kernel 3: FC GEMM (gathered A) -> g_fc fp32 ----------------
__global__ void __launch_bounds__(512, 1) fc_mma_kernel() {
    extern __shared__ char sm[];
    __shared__ int trow[A_ROWS];
    int e = blockIdx.z, cnt = g_cnt[e];
    int m0 = blockIdx.y * A_ROWS;
    if (m0 >= cnt) return;
    int n0 = blockIdx.x * B_ROWS;
    int tid = threadIdx.x;
    if (tid < A_ROWS) { int gi = m0 + tid; trow[tid] = g_list[e][gi < cnt ? gi : cnt - 1]; }
    __syncthreads();
    uint32_t sb = smem_u32(sm);

    int arow = tid >> 1, aoff = (tid & 1) * 32;
    int brow = tid >> 2, boff = (tid & 3) * 16;
    int tok = trow[arow];
    GemmPtrs p;
    p.gAh = (const char*)(g_x_hi + (size_t)tok * HD) + aoff;
    p.gAl = (const char*)(g_x_lo + (size_t)tok * HD) + aoff;
    size_t br = ((size_t)e * 2 * ID + n0 + brow) * HD;
    p.gBh = (const char*)(g_wfc_hi + br) + boff;
    p.gBl = (const char*)(g_wfc_lo + br) + boff;
    uint32_t sd_a = sb + arow * ROWB + aoff;
    uint32_t sd_b = sb + 2 * A_T + brow * ROWB + boff;

    int wid = tid >> 5, lane = tid & 31;
    int wm = (wid & 3) * 64, wn = (wid >> 2) * 32;
    uint32_t a_base = sb + (wm + (lane & 15)) * ROWB + ((lane & 16) ? 16 : 0);
    uint32_t b_base = sb + 2 * A_T + (wn + (lane & 7)) * ROWB + ((lane & 8) ? 16 : 0);

    float acc[4][4][4];
#pragma unroll
    for (int mt = 0; mt < 4; mt++)
#pragma unroll
        for (int nt = 0; nt < 4; nt++)
#pragma unroll
            for (int k = 0; k < 4; k++) acc[mt][nt][k] = 0.f;

    gemm_mainloop(sb, p, sd_a, sd_b, HD / KC, acc, a_base, b_base);

    int g = lane >> 2, t = lane & 3;
    int roff = g_off[e];
#pragma unroll
    for (int mt = 0; mt < 4; mt++) {
#pragma unroll
        for (int half = 0; half < 2; half++) {
            int r = wm + mt * 16 + g + half * 8;
            int gi = m0 + r;
            if (gi < cnt) {
                float* orow = g_fc + (size_t)(roff + gi) * 2048 + n0 + wn;
#pragma unroll
                for (int nt = 0; nt < 4; nt++) {
                    float2 v = half ? make_float2(acc[mt][nt][2], acc[mt][nt][3])
                                    : make_float2(acc[mt][nt][0], acc[mt][nt][1]);
                    *(float2*)(orow + nt * 8 + t * 2) = v;
                }
            }
        }
    }
}

// ---------------- kernel 4: GLU + split -> g_h hi/lo ----------------
__global__ void glu_kernel() {
    int R = g_off[NE];
    int idx = blockIdx.x * blockDim.x + threadIdx.x;
    int r = idx >> 8;
    if (r >= R) return;
    int c = (idx & 255) * 4;
    const float* row = g_fc + (size_t)r * 2048;
    float4 a = *(const float4*)(row + c);
    float4 b = *(const float4*)(row + 1024 + c);
    float fa[4] = {a.x, a.y, a.z, a.w};
    float fb[4] = {b.x, b.y, b.z, b.w};
    size_t o = (size_t)r * ID + c;
    __nv_bfloat16 h[4], l[4];
#pragma unroll
    for (int j = 0; j < 4; j++) {
        float gv = fa[j] / (1.f + expf(-fa[j])) * fb[j];
        h[j] = __float2bfloat16(gv);
        l[j] = __float2bfloat16(gv - __bfloat162float(h[j]));
    }
    __nv_bfloat162 p0, p1;
    p0.x = h[0]; p0.y = h[1]; p1.x = h[2]; p1.y = h[3];
    *(__nv_bfloat162*)(g_h_hi + o) = p0; *(__nv_bfloat162*)(g_h_hi + o + 2) = p1;
    p0.x = l[0]; p0.y = l[1]; p1.x = l[2]; p1.y = l[3];
    *(__nv_bfloat162*)(g_h_lo + o) = p0; *(__nv_bfloat162*)(g_h_lo + o + 2) = p1;
}

// ---------------- kernel 5: proj GEMM -> g_fc fp32 (reused) ----------------
__global__ void __launch_bounds__(512, 1) proj_mma_kernel() {
    extern __shared__ char sm[];
    int e = blockIdx.z, cnt = g_cnt[e];
    int m0 = blockIdx.y * A_ROWS;
    if (m0 >= cnt) return;
    int n0 = blockIdx.x * B_ROWS;
    int tid = threadIdx.x;
    uint32_t sb = smem_u32(sm);
    int roff = g_off[e];

    int arow = tid >> 1, aoff = (tid & 1) * 32;
    int brow = tid >> 2, boff = (tid & 3) * 16;
    int gi0 = m0 + arow;
    int gic = gi0 < cnt ? gi0 : cnt - 1;
    size_t ar = (size_t)(roff + gic) * ID;
    GemmPtrs p;
    p.gAh = (const char*)(g_h_hi + ar) + aoff;
    p.gAl = (const char*)(g_h_lo + ar) + aoff;
    size_t br = ((size_t)e * HD + n0 + brow) * ID;
    p.gBh = (const char*)(g_wp_hi + br) + boff;
    p.gBl = (const char*)(g_wp_lo + br) + boff;
    uint32_t sd_a = sb + arow * ROWB + aoff;
    uint32_t sd_b = sb + 2 * A_T + brow * ROWB + boff;

    int wid = tid >> 5, lane = tid & 31;
    int wm = (wid & 3) * 64, wn = (wid >> 2) * 32;
    uint32_t a_base = sb + (wm + (lane & 15)) * ROWB + ((lane & 16) ? 16 : 0);
    uint32_t b_base = sb + 2 * A_T + (wn + (lane & 7)) * ROWB + ((lane & 8) ? 16 : 0);

    float acc[4][4][4];
#pragma unroll
    for (int mt = 0; mt < 4; mt++)
#pragma unroll
        for (int nt = 0; nt < 4; nt++)
#pragma unroll
            for (int k = 0; k < 4; k++) acc[mt][nt][k] = 0.f;

    gemm_mainloop(sb, p, sd_a, sd_b, ID / KC, acc, a_base, b_base);

    int g = lane >> 2, t = lane & 3;
#pragma unroll
    for (int mt = 0; mt < 4; mt++) {
#pragma unroll
        for (int half = 0; half < 2; half++) {
            int r = wm + mt * 16 + g + half * 8;
            int gi = m0 + r;
            if (gi < cnt) {
                float* orow = g_fc + (size_t)(roff + gi) * 2048 + n0 + wn;
#pragma unroll
                for (int nt = 0; nt < 4; nt++) {
                    float2 v = half ? make_float2(acc[mt][nt][2], acc[mt][nt][3])
                                    : make_float2(acc[mt][nt][0], acc[mt][nt][1]);
                    *(float2*)(orow + nt * 8 + t * 2) = v;
                }
            }
        }
    }
}

// ---------------- kernel 6: combine ----------------
__global__ void combine_kernel(float* __restrict__ out_y, int T) {
    int idx = blockIdx.x * blockDim.x + threadIdx.x;
    int t = idx >> 9;
    if (t >= T) return;
    int c = (idx & 511) * 4;
    int4 s = g_slot[t];
    int r0 = g_off[s.x] + s.y;
    int r1 = g_off[s.z] + s.w;
    float w0 = g_wt[s.x][s.y];
    float w1 = g_wt[s.z][s.w];
    float4 p0 = *(const float4*)(g_fc + (size_t)r0 * 2048 + c);
    float4 p1 = *(const float4*)(g_fc + (size_t)r1 * 2048 + c);
    float4 v;
    v.x = w0 * p0.x + w1 * p1.x;
    v.y = w0 * p0.y + w1 * p1.y;
    v.z = w0 * p0.z + w1 * p1.z;
    v.w = w0 * p0.w + w1 * p1.w;
    *(float4*)(out_y + (size_t)t * HD + c) = v;
}

// ---------------- launch ----------------
extern "C" void kernel_launch(void* const* d_in, const int* in_sizes, int n_in,
                              void* d_out, int out_size) {
    const float* x   = (const float*)d_in[0];
    const float* wg  = (const float*)d_in[1];
    const float* wfc = (const float*)d_in[2];
    const float* wp  = (const float*)d_in[3];
    float* out = (float*)d_out;

    int T = in_sizes[0] / HD;
    if (T > TMAX) T = TMAX;

    float* out_y = out;
    long long need = (long long)T * HD + (long long)T * NE;
    float* out_logits = ((long long)out_size >= need) ? out + (size_t)T * HD : nullptr;

    cudaFuncSetAttribute(fc_mma_kernel,   cudaFuncAttributeMaxDynamicSharedMemorySize, DSMEM);
    cudaFuncSetAttribute(proj_mma_kernel, cudaFuncAttributeMaxDynamicSharedMemorySize, DSMEM);

    zero_cnt_kernel<<<1, 32>>>();
    router_kernel<<<(T * 32 + 255) / 256, 256>>>(x, wg, out_logits, T);
    offsets_kernel<<<1, 32>>>();

    int n4 = (T * HD) / 4;
    split_x_kernel<<<(n4 + 255) / 256, 256>>>(x, n4);
    int n4fc = NE * 2 * ID * HD / 4;
    split_wfc_kernel<<<(n4fc + 255) / 256, 256>>>(wfc, n4fc);
    int n4wp = NE * HD * ID / 4;
    split_wp_kernel<<<(n4wp + 255) / 256, 256>>>(wp, n4wp);

    dim3 g1(2 * ID / B_ROWS, TMAX / A_ROWS, NE);   // (16, 32, 8)
    fc_mma_kernel<<<g1, 512, DSMEM>>>();

    int nglu = RMAX * (ID / 4);
    glu_kernel<<<nglu / 256, 256>>>();

    dim3 g2(HD / B_ROWS, TMAX / A_ROWS, NE);       // (16, 32, 8)
    proj_mma_kernel<<<g2, 512, DSMEM>>>();

    int ncmb = T * (HD / 4);
    combine_kernel<<<(ncmb + 255) / 256, 256>>>(out_y, T);
}

// round 5
// speedup vs baseline: 3.1398x; 1.1302x over previous
#include <cuda_runtime.h>
#include <cuda_bf16.h>
#include <math.h>
#include <stdint.h>

#define NE   8
#define HD   2048
#define ID   1024
#define TMAX 8192
#define RMAX (2*TMAX)

#define KC     32                   // K elems per chunk
#define NST    2                    // pipeline stages
#define ROWB   80                   // smem bytes per tile row (64 data + 16 pad)
#define A_ROWS 128
#define B_ROWS 128
#define A_T    (A_ROWS*ROWB)        // 10240
#define B_T    (B_ROWS*ROWB)        // 10240
#define STG_B  (2*A_T + 2*B_T)      // 40960 per stage (Ahi,Alo,Bhi,Blo)
#define DSMEM  (NST*STG_B)          // 81920 -> 2 CTAs/SM

// ---------------- persistent device scratch ----------------
__device__ int   g_cnt[NE];
__device__ int   g_off[NE + 1];
__device__ int   g_list[NE][TMAX];
__device__ float g_wt[NE][TMAX];
__device__ int4  g_slot[TMAX];
__device__ __align__(256) __nv_bfloat16 g_x_hi[(size_t)TMAX * HD];
__device__ __align__(256) __nv_bfloat16 g_x_lo[(size_t)TMAX * HD];
__device__ __align__(256) __nv_bfloat16 g_wfc_hi[(size_t)NE * 2 * ID * HD];
__device__ __align__(256) __nv_bfloat16 g_wfc_lo[(size_t)NE * 2 * ID * HD];
__device__ __align__(256) __nv_bfloat16 g_wp_hi[(size_t)NE * HD * ID];
__device__ __align__(256) __nv_bfloat16 g_wp_lo[(size_t)NE * HD * ID];
__device__ __align__(256) __nv_bfloat16 g_h_hi[(size_t)RMAX * ID];
__device__ __align__(256) __nv_bfloat16 g_h_lo[(size_t)RMAX * ID];
__device__ __align__(256) float g_fc[(size_t)RMAX * 2048];

// ---------------- PTX helpers ----------------
__device__ __forceinline__ uint32_t smem_u32(const void* p) {
    uint32_t a;
    asm("{ .reg .u64 t; cvta.to.shared.u64 t, %1; cvt.u32.u64 %0, t; }" : "=r"(a) : "l"(p));
    return a;
}
__device__ __forceinline__ void cp16(uint32_t d, const void* s) {
    asm volatile("cp.async.cg.shared.global [%0], [%1], 16;\n" :: "r"(d), "l"(s));
}
#define CP_COMMIT() asm volatile("cp.async.commit_group;\n" ::: "memory")
#define CP_WAIT0()  asm volatile("cp.async.wait_group 0;\n" ::: "memory")

__device__ __forceinline__ void ldsm4(uint32_t r[4], uint32_t addr) {
    asm volatile("ldmatrix.sync.aligned.m8n8.x4.shared.b16 {%0,%1,%2,%3}, [%4];\n"
                 : "=r"(r[0]), "=r"(r[1]), "=r"(r[2]), "=r"(r[3]) : "r"(addr));
}
__device__ __forceinline__ void ldsm2(uint32_t r[2], uint32_t addr) {
    asm volatile("ldmatrix.sync.aligned.m8n8.x2.shared.b16 {%0,%1}, [%2];\n"
                 : "=r"(r[0]), "=r"(r[1]) : "r"(addr));
}
__device__ __forceinline__ void mma_bf16(float c[4], const uint32_t a[4], const uint32_t b[2]) {
    asm volatile(
        "mma.sync.aligned.m16n8k16.row.col.f32.bf16.bf16.f32 "
        "{%0,%1,%2,%3}, {%4,%5,%6,%7}, {%8,%9}, {%0,%1,%2,%3};\n"
        : "+f"(c[0]), "+f"(c[1]), "+f"(c[2]), "+f"(c[3])
        : "r"(a[0]), "r"(a[1]), "r"(a[2]), "r"(a[3]), "r"(b[0]), "r"(b[1]));
}

// ---------------- kernel 0: zero counters ----------------
__global__ void zero_cnt_kernel() {
    if (threadIdx.x < NE) g_cnt[threadIdx.x] = 0;
}

// ---------------- kernel 1: router ----------------
__global__ void router_kernel(const float* __restrict__ x,
                              const float* __restrict__ wg,
                              float* __restrict__ out_logits, int T) {
    int warp = (blockIdx.x * blockDim.x + threadIdx.x) >> 5;
    int lane = threadIdx.x & 31;
    if (warp >= T) return;
    const float* xr = x + (size_t)warp * HD;

    float acc[NE];
#pragma unroll
    for (int e = 0; e < NE; e++) acc[e] = 0.f;
    for (int h = lane; h < HD; h += 32) {
        float xv = xr[h];
#pragma unroll
        for (int e = 0; e < NE; e++) acc[e] = fmaf(xv, wg[e * HD + h], acc[e]);
    }
#pragma unroll
    for (int e = 0; e < NE; e++) {
#pragma unroll
        for (int o = 16; o > 0; o >>= 1)
            acc[e] += __shfl_xor_sync(0xffffffffu, acc[e], o);
    }
    if (out_logits && lane < NE)
        out_logits[(size_t)warp * NE + lane] = acc[lane];
    if (lane == 0) {
        int i0 = 0; float v0 = acc[0];
#pragma unroll
        for (int e = 1; e < NE; e++) if (acc[e] > v0) { v0 = acc[e]; i0 = e; }
        int i1 = -1; float v1 = -1e30f;
#pragma unroll
        for (int e = 0; e < NE; e++) if (e != i0 && acc[e] > v1) { v1 = acc[e]; i1 = e; }
        float e1 = expf(v1 - v0);
        float w0 = 1.f / (1.f + e1);
        float w1 = e1 * w0;
        int p0 = atomicAdd(&g_cnt[i0], 1);
        g_list[i0][p0] = warp; g_wt[i0][p0] = w0;
        int p1 = atomicAdd(&g_cnt[i1], 1);
        g_list[i1][p1] = warp; g_wt[i1][p1] = w1;
        g_slot[warp] = make_int4(i0, p0, i1, p1);
    }
}

// ---------------- kernel 2: prefix offsets ----------------
__global__ void offsets_kernel() {
    if (threadIdx.x == 0) {
        int s = 0;
        for (int e = 0; e < NE; e++) { g_off[e] = s; s += g_cnt[e]; }
        g_off[NE] = s;
    }
}

// ---------------- split: fp32 -> bf16 hi + bf16 lo ----------------
__device__ __forceinline__ void split4_store(float4 v, __nv_bfloat16* hi, __nv_bfloat16* lo, size_t i) {
    float f[4] = {v.x, v.y, v.z, v.w};
    __nv_bfloat16 h[4], l[4];
#pragma unroll
    for (int j = 0; j < 4; j++) {
        h[j] = __float2bfloat16(f[j]);
        l[j] = __float2bfloat16(f[j] - __bfloat162float(h[j]));
    }
    __nv_bfloat162 p0, p1;
    p0.x = h[0]; p0.y = h[1]; p1.x = h[2]; p1.y = h[3];
    *(__nv_bfloat162*)(hi + i) = p0; *(__nv_bfloat162*)(hi + i + 2) = p1;
    p0.x = l[0]; p0.y = l[1]; p1.x = l[2]; p1.y = l[3];
    *(__nv_bfloat162*)(lo + i) = p0; *(__nv_bfloat162*)(lo + i + 2) = p1;
}
__global__ void split_x_kernel(const float* __restrict__ src, int n4) {
    int i = blockIdx.x * blockDim.x + threadIdx.x;
    if (i < n4) split4_store(*(const float4*)(src + (size_t)i * 4), g_x_hi, g_x_lo, (size_t)i * 4);
}
__global__ void split_wfc_kernel(const float* __restrict__ src, int n4) {
    int i = blockIdx.x * blockDim.x + threadIdx.x;
    if (i < n4) split4_store(*(const float4*)(src + (size_t)i * 4), g_wfc_hi, g_wfc_lo, (size_t)i * 4);
}
__global__ void split_wp_kernel(const float* __restrict__ src, int n4) {
    int i = blockIdx.x * blockDim.x + threadIdx.x;
    if (i < n4) split4_store(*(const float4*)(src + (size_t)i * 4), g_wp_hi, g_wp_lo, (size_t)i * 4);
}

// ================= GEMM mainloop (shared by FC and proj) =================
// CTA tile 128x128, 256 threads, 8 warps of 64x32, 3-term bf16 split,
// 2-stage cp.async pipeline, 2 CTAs/SM.
struct GemmPtrs {
    const char *gAh, *gAl, *gBh, *gBl;   // per-thread source base (row+offset applied)
};

__device__ __forceinline__ void gemm_mainloop(
    const GemmPtrs& p, uint32_t sd_a, uint32_t sd_b,
    int NK, float acc[4][4][4],
    uint32_t a_base, uint32_t b_base)
{
    auto load_stage = [&](int s, int kc) {
        uint32_t st = (uint32_t)s * STG_B;
        int go = kc * (KC * 2);
        uint32_t da = sd_a + st;
        cp16(da,        p.gAh + go); cp16(da + 16,        p.gAh + go + 16);
        cp16(da + A_T,  p.gAl + go); cp16(da + A_T + 16,  p.gAl + go + 16);
        uint32_t db = sd_b + st;
        cp16(db,        p.gBh + go); cp16(db + 16,        p.gBh + go + 16);
        cp16(db + B_T,  p.gBl + go); cp16(db + B_T + 16,  p.gBl + go + 16);
    };

    load_stage(0, 0); CP_COMMIT();

    for (int kc = 0; kc < NK; kc++) {
        CP_WAIT0();
        __syncthreads();
        if (kc + 1 < NK) { load_stage((kc + 1) & 1, kc + 1); CP_COMMIT(); }
        uint32_t st = (uint32_t)(kc & 1) * STG_B;
#pragma unroll
        for (int ks = 0; ks < 2; ks++) {
            uint32_t bh[4][2], bl[4][2];
#pragma unroll
            for (int nt = 0; nt < 4; nt++) {
                ldsm2(bh[nt], b_base + st + nt * 8 * ROWB + ks * 32);
                ldsm2(bl[nt], b_base + st + B_T + nt * 8 * ROWB + ks * 32);
            }
#pragma unroll
            for (int mt = 0; mt < 4; mt++) {
                uint32_t ah[4], al[4];
                ldsm4(ah, a_base + st + mt * 16 * ROWB + ks * 32);
                ldsm4(al, a_base + st + A_T + mt * 16 * ROWB + ks * 32);
#pragma unroll
                for (int nt = 0; nt < 4; nt++) {
                    mma_bf16(acc[mt][nt], ah, bh[nt]);
                    mma_bf16(acc[mt][nt], ah, bl[nt]);
                    mma_bf16(acc[mt][nt], al, bh[nt]);
                }
            }
        }
    }
}

// ---------------- kernel 3: FC GEMM (gathered A) -> g_fc fp32 ----------------
__global__ void __launch_bounds__(256, 2) fc_mma_kernel() {
    extern __shared__ char sm[];
    __shared__ int trow[A_ROWS];
    int e = blockIdx.z, cnt = g_cnt[e];
    int m0 = blockIdx.y * A_ROWS;
    if (m0 >= cnt) return;
    int n0 = blockIdx.x * B_ROWS;
    int tid = threadIdx.x;
    if (tid < A_ROWS) { int gi = m0 + tid; trow[tid] = g_list[e][gi < cnt ? gi : cnt - 1]; }
    __syncthreads();
    uint32_t sb = smem_u32(sm);

    int arow = tid >> 1, aoff = (tid & 1) * 32;
    int tok = trow[arow];
    GemmPtrs p;
    p.gAh = (const char*)(g_x_hi + (size_t)tok * HD) + aoff;
    p.gAl = (const char*)(g_x_lo + (size_t)tok * HD) + aoff;
    size_t br = ((size_t)e * 2 * ID + n0 + arow) * HD;
    p.gBh = (const char*)(g_wfc_hi + br) + aoff;
    p.gBl = (const char*)(g_wfc_lo + br) + aoff;
    uint32_t sd_a = sb + arow * ROWB + aoff;
    uint32_t sd_b = sb + 2 * A_T + arow * ROWB + aoff;

    int wid = tid >> 5, lane = tid & 31;
    int wm = (wid & 1) * 64, wn = (wid >> 1) * 32;
    uint32_t a_base = sb + (wm + (lane & 15)) * ROWB + ((lane & 16) ? 16 : 0);
    uint32_t b_base = sb + 2 * A_T + (wn + (lane & 7)) * ROWB + ((lane & 8) ? 16 : 0);

    float acc[4][4][4];
#pragma unroll
    for (int mt = 0; mt < 4; mt++)
#pragma unroll
        for (int nt = 0; nt < 4; nt++)
#pragma unroll
            for (int k = 0; k < 4; k++) acc[mt][nt][k] = 0.f;

    gemm_mainloop(p, sd_a, sd_b, HD / KC, acc, a_base, b_base);

    int g = lane >> 2, t = lane & 3;
    int roff = g_off[e];
#pragma unroll
    for (int mt = 0; mt < 4; mt++) {
#pragma unroll
        for (int half = 0; half < 2; half++) {
            int r = wm + mt * 16 + g + half * 8;
            int gi = m0 + r;
            if (gi < cnt) {
                float* orow = g_fc + (size_t)(roff + gi) * 2048 + n0 + wn;
#pragma unroll
                for (int nt = 0; nt < 4; nt++) {
                    float2 v = half ? make_float2(acc[mt][nt][2], acc[mt][nt][3])
                                    : make_float2(acc[mt][nt][0], acc[mt][nt][1]);
                    *(float2*)(orow + nt * 8 + t * 2) = v;
                }
            }
        }
    }
}

// ---------------- kernel 4: GLU + split -> g_h hi/lo ----------------
__global__ void glu_kernel() {
    int R = g_off[NE];
    int idx = blockIdx.x * blockDim.x + threadIdx.x;
    int r = idx >> 8;
    if (r >= R) return;
    int c = (idx & 255) * 4;
    const float* row = g_fc + (size_t)r * 2048;
    float4 a = *(const float4*)(row + c);
    float4 b = *(const float4*)(row + 1024 + c);
    float fa[4] = {a.x, a.y, a.z, a.w};
    float fb[4] = {b.x, b.y, b.z, b.w};
    size_t o = (size_t)r * ID + c;
    __nv_bfloat16 h[4], l[4];
#pragma unroll
    for (int j = 0; j < 4; j++) {
        float gv = fa[j] / (1.f + expf(-fa[j])) * fb[j];
        h[j] = __float2bfloat16(gv);
        l[j] = __float2bfloat16(gv - __bfloat162float(h[j]));
    }
    __nv_bfloat162 p0, p1;
    p0.x = h[0]; p0.y = h[1]; p1.x = h[2]; p1.y = h[3];
    *(__nv_bfloat162*)(g_h_hi + o) = p0; *(__nv_bfloat162*)(g_h_hi + o + 2) = p1;
    p0.x = l[0]; p0.y = l[1]; p1.x = l[2]; p1.y = l[3];
    *(__nv_bfloat162*)(g_h_lo + o) = p0; *(__nv_bfloat162*)(g_h_lo + o + 2) = p1;
}

// ---------------- kernel 5: proj GEMM -> g_fc fp32 (reused) ----------------
__global__ void __launch_bounds__(256, 2) proj_mma_kernel() {
    extern __shared__ char sm[];
    int e = blockIdx.z, cnt = g_cnt[e];
    int m0 = blockIdx.y * A_ROWS;
    if (m0 >= cnt) return;
    int n0 = blockIdx.x * B_ROWS;
    int tid = threadIdx.x;
    uint32_t sb = smem_u32(sm);
    int roff = g_off[e];

    int arow = tid >> 1, aoff = (tid & 1) * 32;
    int gi0 = m0 + arow;
    int gic = gi0 < cnt ? gi0 : cnt - 1;
    size_t ar = (size_t)(roff + gic) * ID;
    GemmPtrs p;
    p.gAh = (const char*)(g_h_hi + ar) + aoff;
    p.gAl = (const char*)(g_h_lo + ar) + aoff;
    size_t br = ((size_t)e * HD + n0 + arow) * ID;
    p.gBh = (const char*)(g_wp_hi + br) + aoff;
    p.gBl = (const char*)(g_wp_lo + br) + aoff;
    uint32_t sd_a = sb + arow * ROWB + aoff;
    uint32_t sd_b = sb + 2 * A_T + arow * ROWB + aoff;

    int wid = tid >> 5, lane = tid & 31;
    int wm = (wid & 1) * 64, wn = (wid >> 1) * 32;
    uint32_t a_base = sb + (wm + (lane & 15)) * ROWB + ((lane & 16) ? 16 : 0);
    uint32_t b_base = sb + 2 * A_T + (wn + (lane & 7)) * ROWB + ((lane & 8) ? 16 : 0);

    float acc[4][4][4];
#pragma unroll
    for (int mt = 0; mt < 4; mt++)
#pragma unroll
        for (int nt = 0; nt < 4; nt++)
#pragma unroll
            for (int k = 0; k < 4; k++) acc[mt][nt][k] = 0.f;

    gemm_mainloop(p, sd_a, sd_b, ID / KC, acc, a_base, b_base);

    int g = lane >> 2, t = lane & 3;
#pragma unroll
    for (int mt = 0; mt < 4; mt++) {
#pragma unroll
        for (int half = 0; half < 2; half++) {
            int r = wm + mt * 16 + g + half * 8;
            int gi = m0 + r;
            if (gi < cnt) {
                float* orow = g_fc + (size_t)(roff + gi) * 2048 + n0 + wn;
#pragma unroll
                for (int nt = 0; nt < 4; nt++) {
                    float2 v = half ? make_float2(acc[mt][nt][2], acc[mt][nt][3])
                                    : make_float2(acc[mt][nt][0], acc[mt][nt][1]);
                    *(float2*)(orow + nt * 8 + t * 2) = v;
                }
            }
        }
    }
}

// ---------------- kernel 6: combine ----------------
__global__ void combine_kernel(float* __restrict__ out_y, int T) {
    int idx = blockIdx.x * blockDim.x + threadIdx.x;
    int t = idx >> 9;
    if (t >= T) return;
    int c = (idx & 511) * 4;
    int4 s = g_slot[t];
    int r0 = g_off[s.x] + s.y;
    int r1 = g_off[s.z] + s.w;
    float w0 = g_wt[s.x][s.y];
    float w1 = g_wt[s.z][s.w];
    float4 p0 = *(const float4*)(g_fc + (size_t)r0 * 2048 + c);
    float4 p1 = *(const float4*)(g_fc + (size_t)r1 * 2048 + c);
    float4 v;
    v.x = w0 * p0.x + w1 * p1.x;
    v.y = w0 * p0.y + w1 * p1.y;
    v.z = w0 * p0.z + w1 * p1.z;
    v.w = w0 * p0.w + w1 * p1.w;
    *(float4*)(out_y + (size_t)t * HD + c) = v;
}

// ---------------- launch ----------------
extern "C" void kernel_launch(void* const* d_in, const int* in_sizes, int n_in,
                              void* d_out, int out_size) {
    const float* x   = (const float*)d_in[0];
    const float* wg  = (const float*)d_in[1];
    const float* wfc = (const float*)d_in[2];
    const float* wp  = (const float*)d_in[3];
    float* out = (float*)d_out;

    int T = in_sizes[0] / HD;
    if (T > TMAX) T = TMAX;

    float* out_y = out;
    long long need = (long long)T * HD + (long long)T * NE;
    float* out_logits = ((long long)out_size >= need) ? out + (size_t)T * HD : nullptr;

    cudaFuncSetAttribute(fc_mma_kernel,   cudaFuncAttributeMaxDynamicSharedMemorySize, DSMEM);
    cudaFuncSetAttribute(proj_mma_kernel, cudaFuncAttributeMaxDynamicSharedMemorySize, DSMEM);

    zero_cnt_kernel<<<1, 32>>>();
    router_kernel<<<(T * 32 + 255) / 256, 256>>>(x, wg, out_logits, T);
    offsets_kernel<<<1, 32>>>();

    int n4 = (T * HD) / 4;
    split_x_kernel<<<(n4 + 255) / 256, 256>>>(x, n4);
    int n4fc = NE * 2 * ID * HD / 4;
    split_wfc_kernel<<<(n4fc + 255) / 256, 256>>>(wfc, n4fc);
    int n4wp = NE * HD * ID / 4;
    split_wp_kernel<<<(n4wp + 255) / 256, 256>>>(wp, n4wp);

    dim3 g1(2 * ID / B_ROWS, TMAX / A_ROWS, NE);   // (16, 64, 8)
    fc_mma_kernel<<<g1, 256, DSMEM>>>();

    int nglu = RMAX * (ID / 4);
    glu_kernel<<<nglu / 256, 256>>>();

    dim3 g2(HD / B_ROWS, TMAX / A_ROWS, NE);       // (16, 64, 8)
    proj_mma_kernel<<<g2, 256, DSMEM>>>();

    int ncmb = T * (HD / 4);
    combine_kernel<<<(ncmb + 255) / 256, 256>>>(out_y, T);
}

// round 6
// speedup vs baseline: 3.4117x; 1.0866x over previous
#include <cuda_runtime.h>
#include <cuda_bf16.h>
#include <math.h>
#include <stdint.h>

#define NE   8
#define HD   2048
#define ID   1024
#define TMAX 8192
#define RMAX (2*TMAX)

#define KC     32                   // K elems per chunk (64 bytes)
#define NST    3                    // pipeline stages
#define ROWB   64                   // smem bytes per tile row (swizzled, no pad)
#define A_ROWS 128
#define B_ROWS 128
#define A_T    (A_ROWS*ROWB)        // 8192
#define STG_B  (4*A_T)              // 32768 per stage (Ahi,Alo,Bhi,Blo)
#define DSMEM  (NST*STG_B)          // 98304 -> 2 CTAs/SM

// ---------------- persistent device scratch ----------------
__device__ int   g_cnt[NE];
__device__ int   g_off[NE + 1];
__device__ int   g_list[NE][TMAX];
__device__ float g_wt[NE][TMAX];
__device__ int4  g_slot[TMAX];
__device__ __align__(256) __nv_bfloat16 g_x_hi[(size_t)TMAX * HD];
__device__ __align__(256) __nv_bfloat16 g_x_lo[(size_t)TMAX * HD];
__device__ __align__(256) __nv_bfloat16 g_wfc_hi[(size_t)NE * 2 * ID * HD];
__device__ __align__(256) __nv_bfloat16 g_wfc_lo[(size_t)NE * 2 * ID * HD];
__device__ __align__(256) __nv_bfloat16 g_wp_hi[(size_t)NE * HD * ID];
__device__ __align__(256) __nv_bfloat16 g_wp_lo[(size_t)NE * HD * ID];
__device__ __align__(256) __nv_bfloat16 g_h_hi[(size_t)RMAX * ID];
__device__ __align__(256) __nv_bfloat16 g_h_lo[(size_t)RMAX * ID];
__device__ __align__(256) float g_fc[(size_t)RMAX * 2048];

// ---------------- PTX helpers ----------------
__device__ __forceinline__ uint32_t smem_u32(const void* p) {
    uint32_t a;
    asm("{ .reg .u64 t; cvta.to.shared.u64 t, %1; cvt.u32.u64 %0, t; }" : "=r"(a) : "l"(p));
    return a;
}
__device__ __forceinline__ void cp16(uint32_t d, const void* s) {
    asm volatile("cp.async.cg.shared.global [%0], [%1], 16;\n" :: "r"(d), "l"(s));
}
#define CP_COMMIT() asm volatile("cp.async.commit_group;\n" ::: "memory")
#define CP_WAIT1()  asm volatile("cp.async.wait_group 1;\n" ::: "memory")

__device__ __forceinline__ void ldsm4(uint32_t r[4], uint32_t addr) {
    asm volatile("ldmatrix.sync.aligned.m8n8.x4.shared.b16 {%0,%1,%2,%3}, [%4];\n"
                 : "=r"(r[0]), "=r"(r[1]), "=r"(r[2]), "=r"(r[3]) : "r"(addr));
}
__device__ __forceinline__ void mma_bf16(float c[4], const uint32_t a[4], const uint32_t b[2]) {
    asm volatile(
        "mma.sync.aligned.m16n8k16.row.col.f32.bf16.bf16.f32 "
        "{%0,%1,%2,%3}, {%4,%5,%6,%7}, {%8,%9}, {%0,%1,%2,%3};\n"
        : "+f"(c[0]), "+f"(c[1]), "+f"(c[2]), "+f"(c[3])
        : "r"(a[0]), "r"(a[1]), "r"(a[2]), "r"(a[3]), "r"(b[0]), "r"(b[1]));
}

// ---------------- kernel 0: fused split (x, wfc, wp) + zero counters ----------------
__device__ __forceinline__ void split4_store(float4 v, __nv_bfloat16* hi, __nv_bfloat16* lo, size_t i) {
    float f[4] = {v.x, v.y, v.z, v.w};
    __nv_bfloat16 h[4], l[4];
#pragma unroll
    for (int j = 0; j < 4; j++) {
        h[j] = __float2bfloat16(f[j]);
        l[j] = __float2bfloat16(f[j] - __bfloat162float(h[j]));
    }
    __nv_bfloat162 p0, p1;
    p0.x = h[0]; p0.y = h[1]; p1.x = h[2]; p1.y = h[3];
    *(__nv_bfloat162*)(hi + i) = p0; *(__nv_bfloat162*)(hi + i + 2) = p1;
    p0.x = l[0]; p0.y = l[1]; p1.x = l[2]; p1.y = l[3];
    *(__nv_bfloat162*)(lo + i) = p0; *(__nv_bfloat162*)(lo + i + 2) = p1;
}

#define X4   ((size_t)TMAX * HD / 4)
#define WFC4 ((size_t)NE * 2 * ID * HD / 4)
#define WP4  ((size_t)NE * HD * ID / 4)

__global__ void fused_split_kernel(const float* __restrict__ x,
                                   const float* __restrict__ wfc,
                                   const float* __restrict__ wp) {
    if (blockIdx.x == 0 && threadIdx.x < NE) g_cnt[threadIdx.x] = 0;
    size_t i = (size_t)blockIdx.x * blockDim.x + threadIdx.x;
    if (i < X4) {
        split4_store(*(const float4*)(x + i * 4), g_x_hi, g_x_lo, i * 4);
    } else if (i < X4 + WFC4) {
        size_t j = i - X4;
        split4_store(*(const float4*)(wfc + j * 4), g_wfc_hi, g_wfc_lo, j * 4);
    } else if (i < X4 + WFC4 + WP4) {
        size_t j = i - X4 - WFC4;
        split4_store(*(const float4*)(wp + j * 4), g_wp_hi, g_wp_lo, j * 4);
    }
}

// ---------------- kernel 1: router ----------------
__global__ void router_kernel(const float* __restrict__ x,
                              const float* __restrict__ wg,
                              float* __restrict__ out_logits, int T) {
    int warp = (blockIdx.x * blockDim.x + threadIdx.x) >> 5;
    int lane = threadIdx.x & 31;
    if (warp >= T) return;
    const float* xr = x + (size_t)warp * HD;

    float acc[NE];
#pragma unroll
    for (int e = 0; e < NE; e++) acc[e] = 0.f;
    for (int h = lane; h < HD; h += 32) {
        float xv = xr[h];
#pragma unroll
        for (int e = 0; e < NE; e++) acc[e] = fmaf(xv, wg[e * HD + h], acc[e]);
    }
#pragma unroll
    for (int e = 0; e < NE; e++) {
#pragma unroll
        for (int o = 16; o > 0; o >>= 1)
            acc[e] += __shfl_xor_sync(0xffffffffu, acc[e], o);
    }
    if (out_logits && lane < NE)
        out_logits[(size_t)warp * NE + lane] = acc[lane];
    if (lane == 0) {
        int i0 = 0; float v0 = acc[0];
#pragma unroll
        for (int e = 1; e < NE; e++) if (acc[e] > v0) { v0 = acc[e]; i0 = e; }
        int i1 = -1; float v1 = -1e30f;
#pragma unroll
        for (int e = 0; e < NE; e++) if (e != i0 && acc[e] > v1) { v1 = acc[e]; i1 = e; }
        float e1 = expf(v1 - v0);
        float w0 = 1.f / (1.f + e1);
        float w1 = e1 * w0;
        int p0 = atomicAdd(&g_cnt[i0], 1);
        g_list[i0][p0] = warp; g_wt[i0][p0] = w0;
        int p1 = atomicAdd(&g_cnt[i1], 1);
        g_list[i1][p1] = warp; g_wt[i1][p1] = w1;
        g_slot[warp] = make_int4(i0, p0, i1, p1);
    }
}

// ---------------- kernel 2: prefix offsets ----------------
__global__ void offsets_kernel() {
    if (threadIdx.x == 0) {
        int s = 0;
        for (int e = 0; e < NE; e++) { g_off[e] = s; s += g_cnt[e]; }
        g_off[NE] = s;
    }
}

// ================= GEMM mainloop =================
// CTA 128x128, 256 threads, 8 warps of 64x32, 3-term bf16 split.
// 64B smem rows with XOR-swizzle (chunk ^= (row>>1)&3), 3-stage cp.async, 2 CTAs/SM.
struct GemmPtrs {
    const char *gAh, *gAl, *gBh, *gBl;   // per-thread row base
};

__device__ __forceinline__ void gemm_mainloop(
    uint32_t sb, const GemmPtrs& p, int tid,
    int NK, float acc[4][4][4])
{
    // loader: thread t -> row t>>1, chunks {2(t&1), 2(t&1)+1}
    int arow = tid >> 1;
    int c0   = (tid & 1) * 2;
    int sr   = (arow >> 1) & 3;
    uint32_t dRow = sb + (uint32_t)arow * ROWB;
    uint32_t d0 = dRow + ((uint32_t)(c0 ^ sr) << 4);
    uint32_t d1 = dRow + ((uint32_t)((c0 + 1) ^ sr) << 4);
    int s0 = c0 * 16, s1 = s0 + 16;

    auto load_stage = [&](int s, int kc) {
        uint32_t st = (uint32_t)s * STG_B;
        int go = kc * (KC * 2);
        cp16(d0 + st,            p.gAh + go + s0); cp16(d1 + st,            p.gAh + go + s1);
        cp16(d0 + st + A_T,      p.gAl + go + s0); cp16(d1 + st + A_T,      p.gAl + go + s1);
        cp16(d0 + st + 2 * A_T,  p.gBh + go + s0); cp16(d1 + st + 2 * A_T,  p.gBh + go + s1);
        cp16(d0 + st + 3 * A_T,  p.gBl + go + s0); cp16(d1 + st + 3 * A_T,  p.gBl + go + s1);
    };

    int wid = tid >> 5, lane = tid & 31;
    int wm = (wid & 1) * 64, wn = (wid >> 1) * 32;
    // A fragment addressing (ldsm4 16x16): row = wm + mt*16 + (lane&15), chunk = 2ks + (lane>>4)&1
    uint32_t aBase = sb + (uint32_t)(wm + (lane & 15)) * ROWB;
    uint32_t sA = ((lane & 15) >> 1) & 3;
    uint32_t hA = (lane >> 4) & 1;
    // B fragment addressing (ldsm4 over two 8-row n-tiles): row = wn + p*16 + 8*((lane>>4)&1) + (lane&7)
    uint32_t bBase = sb + 2 * A_T + (uint32_t)(wn + 8 * ((lane >> 4) & 1) + (lane & 7)) * ROWB;
    uint32_t sB = ((lane & 7) >> 1) & 3;
    uint32_t hB = (lane >> 3) & 1;

    load_stage(0, 0); CP_COMMIT();
    load_stage(1, 1); CP_COMMIT();

    for (int kc = 0; kc < NK; kc++) {
        CP_WAIT1();
        __syncthreads();
        int kn = kc + 2;
        if (kn < NK) load_stage(kn % NST, kn);
        CP_COMMIT();
        uint32_t st = (uint32_t)(kc % NST) * STG_B;
#pragma unroll
        for (int ks = 0; ks < 2; ks++) {
            uint32_t ca = ((2u * ks + hA) ^ sA) << 4;
            uint32_t cb = ((2u * ks + hB) ^ sB) << 4;
            uint32_t bh[8], bl[8];
            ldsm4(bh,     bBase + st + cb);            // n-tiles 0,1 (hi)
            ldsm4(bh + 4, bBase + st + 1024 + cb);     // n-tiles 2,3 (hi)
            ldsm4(bl,     bBase + st + A_T + cb);      // lo
            ldsm4(bl + 4, bBase + st + A_T + 1024 + cb);
#pragma unroll
            for (int mt = 0; mt < 4; mt++) {
                uint32_t ah[4], al[4];
                ldsm4(ah, aBase + st + mt * 1024 + ca);
                ldsm4(al, aBase + st + A_T + mt * 1024 + ca);
#pragma unroll
                for (int nt = 0; nt < 4; nt++) {
                    mma_bf16(acc[mt][nt], ah, bh + 2 * nt);
                    mma_bf16(acc[mt][nt], ah, bl + 2 * nt);
                    mma_bf16(acc[mt][nt], al, bh + 2 * nt);
                }
            }
        }
    }
}

// ---------------- kernel 3: FC GEMM (gathered A) -> g_fc fp32 ----------------
__global__ void __launch_bounds__(256, 2) fc_mma_kernel() {
    extern __shared__ char sm[];
    __shared__ int trow[A_ROWS];
    int e = blockIdx.z, cnt = g_cnt[e];
    int m0 = blockIdx.y * A_ROWS;
    if (m0 >= cnt) return;
    int n0 = blockIdx.x * B_ROWS;
    int tid = threadIdx.x;
    if (tid < A_ROWS) { int gi = m0 + tid; trow[tid] = g_list[e][gi < cnt ? gi : cnt - 1]; }
    __syncthreads();
    uint32_t sb = smem_u32(sm);

    int arow = tid >> 1;
    int tok = trow[arow];
    GemmPtrs p;
    p.gAh = (const char*)(g_x_hi + (size_t)tok * HD);
    p.gAl = (const char*)(g_x_lo + (size_t)tok * HD);
    size_t br = ((size_t)e * 2 * ID + n0 + arow) * HD;
    p.gBh = (const char*)(g_wfc_hi + br);
    p.gBl = (const char*)(g_wfc_lo + br);

    float acc[4][4][4];
#pragma unroll
    for (int mt = 0; mt < 4; mt++)
#pragma unroll
        for (int nt = 0; nt < 4; nt++)
#pragma unroll
            for (int k = 0; k < 4; k++) acc[mt][nt][k] = 0.f;

    gemm_mainloop(sb, p, tid, HD / KC, acc);

    int wid = tid >> 5, lane = tid & 31;
    int wm = (wid & 1) * 64, wn = (wid >> 1) * 32;
    int g = lane >> 2, t = lane & 3;
    int roff = g_off[e];
#pragma unroll
    for (int mt = 0; mt < 4; mt++) {
#pragma unroll
        for (int half = 0; half < 2; half++) {
            int r = wm + mt * 16 + g + half * 8;
            int gi = m0 + r;
            if (gi < cnt) {
                float* orow = g_fc + (size_t)(roff + gi) * 2048 + n0 + wn;
#pragma unroll
                for (int nt = 0; nt < 4; nt++) {
                    float2 v = half ? make_float2(acc[mt][nt][2], acc[mt][nt][3])
                                    : make_float2(acc[mt][nt][0], acc[mt][nt][1]);
                    *(float2*)(orow + nt * 8 + t * 2) = v;
                }
            }
        }
    }
}

// ---------------- kernel 4: GLU + split -> g_h hi/lo ----------------
__global__ void glu_kernel() {
    int R = g_off[NE];
    int idx = blockIdx.x * blockDim.x + threadIdx.x;
    int r = idx >> 8;
    if (r >= R) return;
    int c = (idx & 255) * 4;
    const float* row = g_fc + (size_t)r * 2048;
    float4 a = *(const float4*)(row + c);
    float4 b = *(const float4*)(row + 1024 + c);
    float fa[4] = {a.x, a.y, a.z, a.w};
    float fb[4] = {b.x, b.y, b.z, b.w};
    size_t o = (size_t)r * ID + c;
    __nv_bfloat16 h[4], l[4];
#pragma unroll
    for (int j = 0; j < 4; j++) {
        float gv = fa[j] / (1.f + expf(-fa[j])) * fb[j];
        h[j] = __float2bfloat16(gv);
        l[j] = __float2bfloat16(gv - __bfloat162float(h[j]));
    }
    __nv_bfloat162 p0, p1;
    p0.x = h[0]; p0.y = h[1]; p1.x = h[2]; p1.y = h[3];
    *(__nv_bfloat162*)(g_h_hi + o) = p0; *(__nv_bfloat162*)(g_h_hi + o + 2) = p1;
    p0.x = l[0]; p0.y = l[1]; p1.x = l[2]; p1.y = l[3];
    *(__nv_bfloat162*)(g_h_lo + o) = p0; *(__nv_bfloat162*)(g_h_lo + o + 2) = p1;
}

// ---------------- kernel 5: proj GEMM -> g_fc fp32 (reused) ----------------
__global__ void __launch_bounds__(256, 2) proj_mma_kernel() {
    extern __shared__ char sm[];
    int e = blockIdx.z, cnt = g_cnt[e];
    int m0 = blockIdx.y * A_ROWS;
    if (m0 >= cnt) return;
    int n0 = blockIdx.x * B_ROWS;
    int tid = threadIdx.x;
    uint32_t sb = smem_u32(sm);
    int roff = g_off[e];

    int arow = tid >> 1;
    int gi0 = m0 + arow;
    int gic = gi0 < cnt ? gi0 : cnt - 1;
    size_t ar = (size_t)(roff + gic) * ID;
    GemmPtrs p;
    p.gAh = (const char*)(g_h_hi + ar);
    p.gAl = (const char*)(g_h_lo + ar);
    size_t br = ((size_t)e * HD + n0 + arow) * ID;
    p.gBh = (const char*)(g_wp_hi + br);
    p.gBl = (const char*)(g_wp_lo + br);

    float acc[4][4][4];
#pragma unroll
    for (int mt = 0; mt < 4; mt++)
#pragma unroll
        for (int nt = 0; nt < 4; nt++)
#pragma unroll
            for (int k = 0; k < 4; k++) acc[mt][nt][k] = 0.f;

    gemm_mainloop(sb, p, tid, ID / KC, acc);

    int wid = tid >> 5, lane = tid & 31;
    int wm = (wid & 1) * 64, wn = (wid >> 1) * 32;
    int g = lane >> 2, t = lane & 3;
#pragma unroll
    for (int mt = 0; mt < 4; mt++) {
#pragma unroll
        for (int half = 0; half < 2; half++) {
            int r = wm + mt * 16 + g + half * 8;
            int gi = m0 + r;
            if (gi < cnt) {
                float* orow = g_fc + (size_t)(roff + gi) * 2048 + n0 + wn;
#pragma unroll
                for (int nt = 0; nt < 4; nt++) {
                    float2 v = half ? make_float2(acc[mt][nt][2], acc[mt][nt][3])
                                    : make_float2(acc[mt][nt][0], acc[mt][nt][1]);
                    *(float2*)(orow + nt * 8 + t * 2) = v;
                }
            }
        }
    }
}

// ---------------- kernel 6: combine ----------------
__global__ void combine_kernel(float* __restrict__ out_y, int T) {
    int idx = blockIdx.x * blockDim.x + threadIdx.x;
    int t = idx >> 9;
    if (t >= T) return;
    int c = (idx & 511) * 4;
    int4 s = g_slot[t];
    int r0 = g_off[s.x] + s.y;
    int r1 = g_off[s.z] + s.w;
    float w0 = g_wt[s.x][s.y];
    float w1 = g_wt[s.z][s.w];
    float4 p0 = *(const float4*)(g_fc + (size_t)r0 * 2048 + c);
    float4 p1 = *(const float4*)(g_fc + (size_t)r1 * 2048 + c);
    float4 v;
    v.x = w0 * p0.x + w1 * p1.x;
    v.y = w0 * p0.y + w1 * p1.y;
    v.z = w0 * p0.z + w1 * p1.z;
    v.w = w0 * p0.w + w1 * p1.w;
    *(float4*)(out_y + (size_t)t * HD + c) = v;
}

// ---------------- launch ----------------
extern "C" void kernel_launch(void* const* d_in, const int* in_sizes, int n_in,
                              void* d_out, int out_size) {
    const float* x   = (const float*)d_in[0];
    const float* wg  = (const float*)d_in[1];
    const float* wfc = (const float*)d_in[2];
    const float* wp  = (const float*)d_in[3];
    float* out = (float*)d_out;

    int T = in_sizes[0] / HD;
    if (T > TMAX) T = TMAX;

    float* out_y = out;
    long long need = (long long)T * HD + (long long)T * NE;
    float* out_logits = ((long long)out_size >= need) ? out + (size_t)T * HD : nullptr;

    cudaFuncSetAttribute(fc_mma_kernel,   cudaFuncAttributeMaxDynamicSharedMemorySize, DSMEM);
    cudaFuncSetAttribute(proj_mma_kernel, cudaFuncAttributeMaxDynamicSharedMemorySize, DSMEM);

    size_t nsplit4 = X4 + WFC4 + WP4;
    fused_split_kernel<<<(unsigned)((nsplit4 + 255) / 256), 256>>>(x, wfc, wp);
    router_kernel<<<(T * 32 + 255) / 256, 256>>>(x, wg, out_logits, T);
    offsets_kernel<<<1, 32>>>();

    dim3 g1(2 * ID / B_ROWS, TMAX / A_ROWS, NE);   // (16, 64, 8)
    fc_mma_kernel<<<g1, 256, DSMEM>>>();

    int nglu = RMAX * (ID / 4);
    glu_kernel<<<nglu / 256, 256>>>();

    dim3 g2(HD / B_ROWS, TMAX / A_ROWS, NE);       // (16, 64, 8)
    proj_mma_kernel<<<g2, 256, DSMEM>>>();

    int ncmb = T * (HD / 4);
    combine_kernel<<<(ncmb + 255) / 256, 256>>>(out_y, T);
}